// round 3
// baseline (speedup 1.0000x reference)
#include <cuda_runtime.h>
#include <math.h>

#define NB 4096
#define NT 8192
#define DD 256
#define CC 31
#define TILES 64          // 8192 / 128
#define NTILEPAIRS 2080   // TILES*(TILES+1)/2
#define PITCH 132
#define SMEM_FLOATS (4*32*PITCH + 128 + 128 + 8)
#define SMEM_BYTES (SMEM_FLOATS * 4)

// ---------------- device scratch (no allocations allowed) ----------------
__device__ float  g_sq[NT];
__device__ float  g_colpart[64][DD];
__device__ float  g_tpart[16][CC];
__device__ float  g_V[NT * 32];
__device__ int    g_scnt[CC];
__device__ int    g_tpresent[CC];
__device__ float  g_sScale[32];
__device__ float  g_tScale[32];
__device__ float  g_coef[5];
__device__ float  g_c0;
__device__ int    g_chain;
__device__ float  g_inv_nidx;
__device__ double g_loss;

__device__ __forceinline__ float ex2f(float x) {
    float y;
    asm("ex2.approx.ftz.f32 %0, %1;" : "=f"(y) : "f"(x));
    return y;
}

// ---------------- K0: zero the atomic targets ----------------
__global__ void k_init() {
    int t = threadIdx.x;
    if (t < CC) { g_scnt[t] = 0; g_tpresent[t] = 0; }
    if (t == 0) g_loss = 0.0;
}

// ---------------- K1: per-block column-sum partials ----------------
__global__ void k_colsum(const float* __restrict__ src, const float* __restrict__ tgt) {
    int b = blockIdx.x, t = threadIdx.x;
    int r0 = b * 128;
    const float* base = (r0 < NB) ? src + (size_t)r0 * DD
                                  : tgt + (size_t)(r0 - NB) * DD;
    float acc = 0.f;
    for (int r = 0; r < 128; r++) acc += base[(size_t)r * DD + t];
    g_colpart[b][t] = acc;
}

// ---------------- K2: row squared norms (warp per row) ----------------
__global__ void k_sq(const float* __restrict__ src, const float* __restrict__ tgt) {
    int warp = threadIdx.x >> 5, lane = threadIdx.x & 31;
    int row = blockIdx.x * 8 + warp;
    const float* rp = (row < NB) ? src + (size_t)row * DD
                                 : tgt + (size_t)(row - NB) * DD;
    float s = 0.f;
    for (int k = lane; k < DD; k += 32) { float v = rp[k]; s = fmaf(v, v, s); }
#pragma unroll
    for (int off = 16; off; off >>= 1) s += __shfl_xor_sync(0xffffffffu, s, off);
    if (lane == 0) g_sq[row] = s;
}

// ---------------- K3: label statistics (s_label is INT32: jax x64 disabled) ----
__global__ void k_label(const int* __restrict__ s_label,
                        const float* __restrict__ t_label) {
    __shared__ float sh[CC];
    int t = threadIdx.x;
    if (t < CC) sh[t] = 0.f;
    __syncthreads();
    int i = blockIdx.x * 256 + t;   // 16*256 = 4096 threads
    int lbl = s_label[i];
    if (lbl >= 0 && lbl < CC) atomicAdd(&g_scnt[lbl], 1);
    const float* tr = t_label + (size_t)i * CC;
    float best = -1e30f; int arg = 0;
#pragma unroll
    for (int c = 0; c < CC; c++) {
        float v = tr[c];
        atomicAdd(&sh[c], v);
        if (v > best) { best = v; arg = c; }
    }
    g_tpresent[arg] = 1;
    __syncthreads();
    if (t < CC) g_tpart[blockIdx.x][t] = sh[t];
}

// ---------------- K4: finalize scalars (bw, mask, scales) ----------------
__global__ void k_finalize() {
    __shared__ double red[256];
    __shared__ double sMSQ;
    int t = threadIdx.x;

    float m = 0.f;
    for (int b = 0; b < 64; b++) m += g_colpart[b][t];
    red[t] = (double)m * (double)m;
    __syncthreads();
    for (int off = 128; off; off >>= 1) { if (t < off) red[t] += red[t + off]; __syncthreads(); }
    if (t == 0) sMSQ = red[0];
    __syncthreads();

    double s1 = 0.0;
    for (int r = t; r < NT; r += 256) s1 += (double)g_sq[r];
    red[t] = s1;
    __syncthreads();
    for (int off = 128; off; off >>= 1) { if (t < off) red[t] += red[t + off]; __syncthreads(); }

    if (t == 0) {
        double S1 = red[0], MSQ = sMSQ;
        double sum_l2 = 2.0 * (double)NT * S1 - 2.0 * MSQ;
        double bw = sum_l2 / ((double)NT * (double)NT - (double)NT);
        if (bw < 1e-6) bw = 1e-6;
        bw *= 0.25;   // / KERNEL_MUL^(KERNEL_NUM//2) = /4
        g_chain = (bw >= 1e-6) ? 1 : 0;
        const double L2E = 1.4426950408889634;
        for (int i = 0; i < 5; i++) {
            double den = bw * (double)(1 << i);
            if (den < 1e-6) den = 1e-6;
            g_coef[i] = (float)(L2E / den);
        }
        g_c0 = g_coef[4];  // widest kernel (bw*16)
        int nidx = 0;
        for (int c = 0; c < CC; c++) {
            float tc = 0.f;
            for (int b = 0; b < 16; b++) tc += g_tpart[b][c];
            int msk = (g_scnt[c] > 0) && (g_tpresent[c] != 0);
            nidx += msk;
            g_sScale[c] = msk ? 1.0f / (float)g_scnt[c] : 0.f;
            float tdiv = (tc == 0.f) ? 100.f : tc;
            g_tScale[c] = msk ? 1.0f / tdiv : 0.f;
        }
        g_sScale[31] = 0.f; g_tScale[31] = 0.f;
        if (nidx < 1) nidx = 1;
        g_inv_nidx = 1.0f / (float)nidx;
    }
}

// ---------------- K5: build signed weight vectors V[8192][32] ----------------
__global__ void k_buildV(const int* __restrict__ s_label,
                         const float* __restrict__ t_label) {
    int i = blockIdx.x * 256 + threadIdx.x;   // 32*256 = 8192
    float* vr = g_V + (size_t)i * 32;
    if (i < NB) {
#pragma unroll
        for (int c = 0; c < 32; c++) vr[c] = 0.f;
        int lbl = s_label[i];
        if (lbl >= 0 && lbl < CC) vr[lbl] = g_sScale[lbl];
    } else {
        int r = i - NB;
        const float* tr = t_label + (size_t)r * CC;
#pragma unroll
        for (int c = 0; c < CC; c++) vr[c] = -tr[c] * g_tScale[c];
        vr[31] = 0.f;
    }
}

// ---------------- K6: main fused tile kernel ----------------
__device__ __forceinline__ void load_chunk_T(float* dst, const float* __restrict__ src,
                                             int rowStride, int tid) {
#pragma unroll
    for (int q = 0; q < 4; q++) {
        int idx = tid + 256 * q;       // 0..1023
        int row = idx >> 3;
        int c4  = idx & 7;
        float4 v = *reinterpret_cast<const float4*>(src + (size_t)row * rowStride + c4 * 4);
        dst[(c4 * 4 + 0) * PITCH + row] = v.x;
        dst[(c4 * 4 + 1) * PITCH + row] = v.y;
        dst[(c4 * 4 + 2) * PITCH + row] = v.z;
        dst[(c4 * 4 + 3) * PITCH + row] = v.w;
    }
}

__global__ void __launch_bounds__(256, 2)
k_main(const float* __restrict__ src, const float* __restrict__ tgt) {
    extern __shared__ float smem[];
    float* sA   = smem;
    float* sB   = sA  + 32 * PITCH;
    float* sVa  = sB  + 32 * PITCH;
    float* sVb  = sVa + 32 * PITCH;
    float* ssqa = sVb + 32 * PITCH;
    float* ssqb = ssqa + 128;
    float* sred = ssqb + 128;

    // decode upper-triangular tile pair
    int bid = blockIdx.x;
    int ti = 0, rem = bid;
    while (rem >= TILES - ti) { rem -= TILES - ti; ti++; }
    int tj = ti + rem;

    int tid = threadIdx.x;
    int tx = tid & 15, ty = tid >> 4;

    int rA = ti * 128, rB = tj * 128;
    const float* baseA = (rA < NB) ? src + (size_t)rA * DD : tgt + (size_t)(rA - NB) * DD;
    const float* baseB = (rB < NB) ? src + (size_t)rB * DD : tgt + (size_t)(rB - NB) * DD;

    if (tid < 128) { ssqa[tid] = g_sq[rA + tid]; ssqb[tid] = g_sq[rB + tid]; }
    load_chunk_T(sVa, g_V + (size_t)rA * 32, 32, tid);
    load_chunk_T(sVb, g_V + (size_t)rB * 32, 32, tid);

    float acc[8][8];
#pragma unroll
    for (int i = 0; i < 8; i++)
#pragma unroll
        for (int j = 0; j < 8; j++) acc[i][j] = 0.f;

    // ---- Gram: acc = A_tile @ B_tile^T over D=256 in chunks of 32 ----
#pragma unroll 1
    for (int k0 = 0; k0 < DD; k0 += 32) {
        __syncthreads();
        load_chunk_T(sA, baseA + k0, DD, tid);
        load_chunk_T(sB, baseB + k0, DD, tid);
        __syncthreads();
#pragma unroll 8
        for (int kk = 0; kk < 32; kk++) {
            float4 a0 = *reinterpret_cast<float4*>(&sA[kk * PITCH + ty * 8]);
            float4 a1 = *reinterpret_cast<float4*>(&sA[kk * PITCH + ty * 8 + 4]);
            float4 b0 = *reinterpret_cast<float4*>(&sB[kk * PITCH + tx * 8]);
            float4 b1 = *reinterpret_cast<float4*>(&sB[kk * PITCH + tx * 8 + 4]);
            float a[8] = {a0.x, a0.y, a0.z, a0.w, a1.x, a1.y, a1.z, a1.w};
            float b[8] = {b0.x, b0.y, b0.z, b0.w, b1.x, b1.y, b1.z, b1.w};
#pragma unroll
            for (int i = 0; i < 8; i++)
#pragma unroll
                for (int j = 0; j < 8; j++)
                    acc[i][j] = fmaf(a[i], b[j], acc[i][j]);
        }
    }

    // ---- epilogue: l2 -> kernel sum (1 EX2 via x + x^2 + x^4 + x^8 + x^16) ----
    float sqa[8], sqb[8];
#pragma unroll
    for (int i = 0; i < 8; i++) { sqa[i] = ssqa[ty * 8 + i]; sqb[i] = ssqb[tx * 8 + i]; }

    float c0 = g_c0;
    int chain = g_chain;
    float cf0 = 0, cf1 = 0, cf2 = 0, cf3 = 0, cf4 = 0;
    if (!chain) { cf0 = g_coef[0]; cf1 = g_coef[1]; cf2 = g_coef[2]; cf3 = g_coef[3]; cf4 = g_coef[4]; }

#pragma unroll
    for (int i = 0; i < 8; i++)
#pragma unroll
        for (int j = 0; j < 8; j++) {
            float l2 = fmaf(-2.0f, acc[i][j], sqa[i] + sqb[j]);
            l2 = fmaxf(l2, 0.0f);
            float ks;
            if (chain) {
                float x  = ex2f(-l2 * c0);
                float x2 = x * x, x4 = x2 * x2, x8 = x4 * x4;
                ks = x + x2 + x4 + x8 + x8 * x8;
            } else {
                ks = ex2f(-l2 * cf0) + ex2f(-l2 * cf1) + ex2f(-l2 * cf2)
                   + ex2f(-l2 * cf3) + ex2f(-l2 * cf4);
            }
            acc[i][j] = ks;
        }

    // ---- weight contraction: part = sum_ij ks_ij * (Va_i . Vb_j) ----
    float part = 0.f;
#pragma unroll 4
    for (int k = 0; k < 32; k++) {
        float4 va0 = *reinterpret_cast<float4*>(&sVa[k * PITCH + ty * 8]);
        float4 va1 = *reinterpret_cast<float4*>(&sVa[k * PITCH + ty * 8 + 4]);
        float4 vb0 = *reinterpret_cast<float4*>(&sVb[k * PITCH + tx * 8]);
        float4 vb1 = *reinterpret_cast<float4*>(&sVb[k * PITCH + tx * 8 + 4]);
        float va[8] = {va0.x, va0.y, va0.z, va0.w, va1.x, va1.y, va1.z, va1.w};
        float vb[8] = {vb0.x, vb0.y, vb0.z, vb0.w, vb1.x, vb1.y, vb1.z, vb1.w};
#pragma unroll
        for (int i = 0; i < 8; i++) {
            float s = 0.f;
#pragma unroll
            for (int j = 0; j < 8; j++) s = fmaf(acc[i][j], vb[j], s);
            part = fmaf(va[i], s, part);
        }
    }
    if (ti != tj) part *= 2.0f;   // upper-triangular symmetry

    // ---- block reduce + single double atomic per CTA ----
#pragma unroll
    for (int off = 16; off; off >>= 1) part += __shfl_xor_sync(0xffffffffu, part, off);
    if ((tid & 31) == 0) sred[tid >> 5] = part;
    __syncthreads();
    if (tid == 0) {
        float s = 0.f;
#pragma unroll
        for (int w = 0; w < 8; w++) s += sred[w];
        atomicAdd(&g_loss, (double)s);
    }
}

// ---------------- K7: write scalar out ----------------
__global__ void k_out(float* out) {
    out[0] = (float)(g_loss * (double)g_inv_nidx);
}

// ---------------- launch ----------------
extern "C" void kernel_launch(void* const* d_in, const int* in_sizes, int n_in,
                              void* d_out, int out_size) {
    const float* src = (const float*)d_in[0];
    const float* tgt = (const float*)d_in[1];
    const int*   sl  = (const int*)d_in[2];
    const float* tl  = (const float*)d_in[3];
    float* out = (float*)d_out;

    cudaFuncSetAttribute(k_main, cudaFuncAttributeMaxDynamicSharedMemorySize, SMEM_BYTES);

    k_init<<<1, 64>>>();
    k_colsum<<<64, 256>>>(src, tgt);
    k_sq<<<1024, 256>>>(src, tgt);
    k_label<<<16, 256>>>(sl, tl);
    k_finalize<<<1, 256>>>();
    k_buildV<<<32, 256>>>(sl, tl);
    k_main<<<NTILEPAIRS, 256, SMEM_BYTES>>>(src, tgt);
    k_out<<<1, 1>>>(out);
}

// round 6
// speedup vs baseline: 2.6363x; 2.6363x over previous
#include <cuda_runtime.h>
#include <cuda_bf16.h>
#include <cstdint>
#include <cstring>
#include <math.h>

#define NB 4096
#define NT 8192
#define DD 256
#define CC 31
#define TILES 64
#define NTILEPAIRS 2080

// ======================= device scratch =======================
__device__ float  g_sq[NT];
__device__ float  g_colpart[64][DD];
__device__ float  g_tpart[16][CC];
__device__ int    g_scnt[CC];
__device__ int    g_tpresent[CC];
__device__ float  g_sScale[32];
__device__ float  g_tScale[32];
__device__ float  g_coef[5];
__device__ float  g_c0;
__device__ int    g_chain;
__device__ float  g_inv_nidx;
__device__ double g_loss;

__device__ __align__(16) unsigned short g_Xh[NT * DD];
__device__ __align__(16) unsigned short g_Xl[NT * DD];
__device__ __align__(16) unsigned short g_Vh[NT * 32];
__device__ __align__(16) unsigned short g_Vl[NT * 32];

// ======================= helpers =======================
__device__ __forceinline__ float ex2f(float x) {
    float y; asm("ex2.approx.ftz.f32 %0, %1;" : "=f"(y) : "f"(x)); return y;
}
__device__ __forceinline__ uint32_t smem_u32(const void* p) {
    uint32_t a;
    asm("{ .reg .u64 t; cvta.to.shared.u64 t, %1; cvt.u32.u64 %0, t; }" : "=r"(a) : "l"(p));
    return a;
}
#define CP16(dst, src) \
    asm volatile("cp.async.cg.shared.global [%0], [%1], 16;" :: "r"(dst), "l"(src))
#define CP_COMMIT() asm volatile("cp.async.commit_group;" ::: "memory")
#define CP_WAIT1()  asm volatile("cp.async.wait_group 1;" ::: "memory")
#define CP_WAIT0()  asm volatile("cp.async.wait_group 0;" ::: "memory")

__device__ __forceinline__ void ldsm4(uint32_t r[4], uint32_t addr) {
    asm volatile("ldmatrix.sync.aligned.m8n8.x4.shared.b16 {%0,%1,%2,%3}, [%4];"
        : "=r"(r[0]), "=r"(r[1]), "=r"(r[2]), "=r"(r[3]) : "r"(addr));
}
__device__ __forceinline__ void mma16816(float d[4], const uint32_t a[4], const uint32_t b[2]) {
    asm volatile("mma.sync.aligned.m16n8k16.row.col.f32.bf16.bf16.f32 "
        "{%0,%1,%2,%3}, {%4,%5,%6,%7}, {%8,%9}, {%0,%1,%2,%3};"
        : "+f"(d[0]), "+f"(d[1]), "+f"(d[2]), "+f"(d[3])
        : "r"(a[0]), "r"(a[1]), "r"(a[2]), "r"(a[3]), "r"(b[0]), "r"(b[1]));
}

// ======================= smem layout =======================
#define SM_V    0                 // 4 x 16KB : Vah, Val, Vbh, Vbl
#define SM_S0   65536             // stage0: Ah, Al, Bh, Bl x 16KB
#define SM_S1   131072            // stage1
#define SM_SQA  196608
#define SM_SQB  197120
#define SM_RED  197632
#define SMEM_TOTAL 197760

// ======================= prepass kernels =======================
__global__ void k_init() {
    int t = threadIdx.x;
    if (t < CC) { g_scnt[t] = 0; g_tpresent[t] = 0; }
    if (t == 0) g_loss = 0.0;
}

__global__ void k_colsum(const float* __restrict__ src, const float* __restrict__ tgt) {
    int b = blockIdx.x, t = threadIdx.x;
    int r0 = b * 128;
    const float* base = (r0 < NB) ? src + (size_t)r0 * DD : tgt + (size_t)(r0 - NB) * DD;
    float acc = 0.f;
    for (int r = 0; r < 128; r++) acc += base[(size_t)r * DD + t];
    g_colpart[b][t] = acc;
}

__global__ void k_sq(const float* __restrict__ src, const float* __restrict__ tgt) {
    int warp = threadIdx.x >> 5, lane = threadIdx.x & 31;
    int row = blockIdx.x * 8 + warp;
    const float* rp = (row < NB) ? src + (size_t)row * DD : tgt + (size_t)(row - NB) * DD;
    float s = 0.f;
    for (int k = lane; k < DD; k += 32) { float v = rp[k]; s = fmaf(v, v, s); }
#pragma unroll
    for (int off = 16; off; off >>= 1) s += __shfl_xor_sync(0xffffffffu, s, off);
    if (lane == 0) g_sq[row] = s;
}

__global__ void k_split(const float* __restrict__ src, const float* __restrict__ tgt) {
    size_t e = ((size_t)blockIdx.x * 256 + threadIdx.x) * 4;
    const float* p = (e < (size_t)NB * DD) ? src + e : tgt + (e - (size_t)NB * DD);
    float4 x = *(const float4*)p;
    float xs[4] = {x.x, x.y, x.z, x.w};
    unsigned short h[4], l[4];
#pragma unroll
    for (int q = 0; q < 4; q++) {
        __nv_bfloat16 hb = __float2bfloat16(xs[q]);
        float rest = xs[q] - __bfloat162float(hb);
        __nv_bfloat16 lb = __float2bfloat16(rest);
        memcpy(&h[q], &hb, 2); memcpy(&l[q], &lb, 2);
    }
    *(uint2*)(g_Xh + e) = make_uint2((uint32_t)h[0] | ((uint32_t)h[1] << 16),
                                     (uint32_t)h[2] | ((uint32_t)h[3] << 16));
    *(uint2*)(g_Xl + e) = make_uint2((uint32_t)l[0] | ((uint32_t)l[1] << 16),
                                     (uint32_t)l[2] | ((uint32_t)l[3] << 16));
}

__global__ void k_label(const int* __restrict__ s_label, const float* __restrict__ t_label) {
    __shared__ float sh[32];
    int t = threadIdx.x, lane = t & 31;
    if (t < 32) sh[t] = 0.f;
    __syncthreads();
    int i = blockIdx.x * 256 + t;
    int lbl = s_label[i];
    if ((unsigned)lbl < CC) atomicAdd(&g_scnt[lbl], 1);
    const float* tr = t_label + (size_t)i * CC;
    float best = -1e30f; int arg = 0;
#pragma unroll
    for (int c = 0; c < CC; c++) {
        float v = tr[c];
        if (v > best) { best = v; arg = c; }
        float s = v;
#pragma unroll
        for (int off = 16; off; off >>= 1) s += __shfl_xor_sync(0xffffffffu, s, off);
        if (lane == 0) atomicAdd(&sh[c], s);
    }
    g_tpresent[arg] = 1;
    __syncthreads();
    if (t < CC) g_tpart[blockIdx.x][t] = sh[t];
}

__global__ void k_finalize() {
    __shared__ double red[256];
    __shared__ double sMSQ;
    int t = threadIdx.x;

    float m = 0.f;
    for (int b = 0; b < 64; b++) m += g_colpart[b][t];
    red[t] = (double)m * (double)m;
    __syncthreads();
    for (int off = 128; off; off >>= 1) { if (t < off) red[t] += red[t + off]; __syncthreads(); }
    if (t == 0) sMSQ = red[0];
    __syncthreads();

    double s1 = 0.0;
    for (int r = t; r < NT; r += 256) s1 += (double)g_sq[r];
    red[t] = s1;
    __syncthreads();
    for (int off = 128; off; off >>= 1) { if (t < off) red[t] += red[t + off]; __syncthreads(); }

    if (t == 0) {
        double S1 = red[0], MSQ = sMSQ;
        double sum_l2 = 2.0 * (double)NT * S1 - 2.0 * MSQ;
        double bw = sum_l2 / ((double)NT * (double)NT - (double)NT);
        if (bw < 1e-6) bw = 1e-6;
        bw *= 0.25;
        g_chain = (bw >= 1e-6) ? 1 : 0;
        const double L2E = 1.4426950408889634;
        for (int i = 0; i < 5; i++) {
            double den = bw * (double)(1 << i);
            if (den < 1e-6) den = 1e-6;
            g_coef[i] = (float)(L2E / den);
        }
        g_c0 = g_coef[4];
        int nidx = 0;
        for (int c = 0; c < CC; c++) {
            float tc = 0.f;
            for (int b = 0; b < 16; b++) tc += g_tpart[b][c];
            int msk = (g_scnt[c] > 0) && (g_tpresent[c] != 0);
            nidx += msk;
            g_sScale[c] = msk ? 1.0f / (float)g_scnt[c] : 0.f;
            float tdiv = (tc == 0.f) ? 100.f : tc;
            g_tScale[c] = msk ? 1.0f / tdiv : 0.f;
        }
        g_sScale[31] = 0.f; g_tScale[31] = 0.f;
        if (nidx < 1) nidx = 1;
        g_inv_nidx = 1.0f / (float)nidx;
    }
}

__global__ void k_buildV(const int* __restrict__ s_label, const float* __restrict__ t_label) {
    int i = blockIdx.x * 256 + threadIdx.x;
    float v[32];
    if (i < NB) {
#pragma unroll
        for (int c = 0; c < 32; c++) v[c] = 0.f;
        int lbl = s_label[i];
        if ((unsigned)lbl < CC) v[lbl] = g_sScale[lbl];
    } else {
        const float* tr = t_label + (size_t)(i - NB) * CC;
#pragma unroll
        for (int c = 0; c < CC; c++) v[c] = -tr[c] * g_tScale[c];
        v[31] = 0.f;
    }
    unsigned short* vh = g_Vh + (size_t)i * 32;
    unsigned short* vl = g_Vl + (size_t)i * 32;
#pragma unroll
    for (int c = 0; c < 32; c++) {
        __nv_bfloat16 hb = __float2bfloat16(v[c]);
        float rest = v[c] - __bfloat162float(hb);
        __nv_bfloat16 lb = __float2bfloat16(rest);
        unsigned short hu, lu; memcpy(&hu, &hb, 2); memcpy(&lu, &lb, 2);
        vh[c] = hu; vl[c] = lu;
    }
}

// ======================= main tile kernel (mma.sync) =======================
// Issue cp.asyncs for one K-chunk (64 elems) of Ah/Al/Bh/Bl into a stage buffer.
__device__ __forceinline__ void issue_chunk(uint32_t sb, uint32_t stage,
        const unsigned short* Ah, const unsigned short* Al,
        const unsigned short* Bh, const unsigned short* Bl,
        int chunk, int tid) {
    const unsigned short* gp[4] = {Ah, Al, Bh, Bl};
#pragma unroll
    for (int t = 0; t < 4; t++) {
#pragma unroll
        for (int q = 0; q < 2; q++) {
            int idx = q * 512 + tid;                 // 0..1023
            int row = idx >> 3, c16 = idx & 7;
            const unsigned short* src = gp[t] + row * 256 + chunk * 64 + c16 * 8;
            uint32_t dst = sb + stage + t * 16384 + row * 128 + (((c16 ^ (row & 7))) << 4);
            CP16(dst, src);
        }
    }
}

// 3-product (hh, hl, lh) mma accumulation over nks k-steps of 16.
__device__ __forceinline__ void do_mma(uint32_t aH, uint32_t aL, uint32_t bH, uint32_t bL,
                                       int nks, int wm, int wn, int lane,
                                       float acc[2][4][4]) {
    int r16 = lane & 15;
    int cuA = lane >> 4;                 // 0/1
    int cuB = (lane >> 3) & 1;           // 0/1
    int jrow = (lane >> 4) * 8;          // 0/8
#pragma unroll
    for (int ks = 0; ks < 4; ks++) {
        if (ks >= nks) break;
        uint32_t ah[2][4], al[2][4], bh[2][4], bl[2][4];
#pragma unroll
        for (int i = 0; i < 2; i++) {
            int row = wm * 32 + i * 16 + r16;
            uint32_t ro = (uint32_t)(row * 128 + (((ks * 2 + cuA) ^ (row & 7)) << 4));
            ldsm4(ah[i], aH + ro);
            ldsm4(al[i], aL + ro);
        }
#pragma unroll
        for (int p = 0; p < 2; p++) {
            int row = wn * 32 + p * 16 + jrow + (lane & 7);
            uint32_t ro = (uint32_t)(row * 128 + (((ks * 2 + cuB) ^ (row & 7)) << 4));
            ldsm4(bh[p], bH + ro);
            ldsm4(bl[p], bL + ro);
        }
#pragma unroll
        for (int i = 0; i < 2; i++)
#pragma unroll
            for (int j = 0; j < 4; j++) {
                const uint32_t* fh = &bh[j >> 1][(j & 1) * 2];
                const uint32_t* fl = &bl[j >> 1][(j & 1) * 2];
                mma16816(acc[i][j], ah[i], fh);
                mma16816(acc[i][j], ah[i], fl);
                mma16816(acc[i][j], al[i], fh);
            }
    }
}

__global__ void __launch_bounds__(512, 1) k_main() {
    extern __shared__ __align__(1024) char smem[];
    uint32_t sb = smem_u32(smem);
    int tid = threadIdx.x, wid = tid >> 5, lane = tid & 31;
    int wm = wid & 3, wn = wid >> 2;

    // decode upper-triangular tile pair
    int bid = blockIdx.x, ti = 0, rem = bid;
    while (rem >= TILES - ti) { rem -= TILES - ti; ti++; }
    int tj = ti + rem;
    int rA = ti * 128, rB = tj * 128;

    float* ssqa = (float*)(smem + SM_SQA);
    float* ssqb = (float*)(smem + SM_SQB);
    float* sred = (float*)(smem + SM_RED);
    if (tid < 128) ssqa[tid] = g_sq[rA + tid];
    else if (tid < 256) ssqb[tid - 128] = g_sq[rB + tid - 128];

    const unsigned short* Ah = g_Xh + (size_t)rA * 256;
    const unsigned short* Al = g_Xl + (size_t)rA * 256;
    const unsigned short* Bh = g_Xh + (size_t)rB * 256;
    const unsigned short* Bl = g_Xl + (size_t)rB * 256;

    // group0: V tiles + chunk0
    {
        const unsigned short* vp[4] = {g_Vh + (size_t)rA * 32, g_Vl + (size_t)rA * 32,
                                       g_Vh + (size_t)rB * 32, g_Vl + (size_t)rB * 32};
#pragma unroll
        for (int t = 0; t < 4; t++) {
            int row = tid >> 2, c16 = tid & 3;
            const unsigned short* src = vp[t] + row * 32 + c16 * 8;
            uint32_t dst = sb + SM_V + t * 16384 + row * 128 + ((c16 ^ (row & 7)) << 4);
            CP16(dst, src);
        }
        issue_chunk(sb, SM_S0, Ah, Al, Bh, Bl, 0, tid);
        CP_COMMIT();
    }
    // group1: chunk1
    issue_chunk(sb, SM_S1, Ah, Al, Bh, Bl, 1, tid);
    CP_COMMIT();

    float acc[2][4][4], wacc[2][4][4];
#pragma unroll
    for (int i = 0; i < 2; i++)
#pragma unroll
        for (int j = 0; j < 4; j++)
#pragma unroll
            for (int r = 0; r < 4; r++) { acc[i][j][r] = 0.f; wacc[i][j][r] = 0.f; }

#pragma unroll 1
    for (int c = 0; c < 4; c++) {
        if (c < 3) { CP_WAIT1(); } else { CP_WAIT0(); }
        __syncthreads();
        uint32_t st = sb + ((c & 1) ? SM_S1 : SM_S0);
        do_mma(st, st + 16384, st + 32768, st + 49152, 4, wm, wn, lane, acc);
        if (c < 2) {
            __syncthreads();
            issue_chunk(sb, (c & 1) ? SM_S1 : SM_S0, Ah, Al, Bh, Bl, c + 2, tid);
            CP_COMMIT();
        }
    }

    // W = Va . Vb^T (K=32 -> 2 ksteps)
    do_mma(sb + SM_V, sb + SM_V + 16384, sb + SM_V + 32768, sb + SM_V + 49152,
           2, wm, wn, lane, wacc);

    // ---- epilogue ----
    float sqa_r[4], sqb_c[8];
#pragma unroll
    for (int i = 0; i < 2; i++)
#pragma unroll
        for (int rh = 0; rh < 2; rh++)
            sqa_r[i * 2 + rh] = ssqa[wm * 32 + i * 16 + (lane >> 2) + rh * 8];
#pragma unroll
    for (int j = 0; j < 4; j++)
#pragma unroll
        for (int cc2 = 0; cc2 < 2; cc2++)
            sqb_c[j * 2 + cc2] = ssqb[wn * 32 + j * 8 + (lane & 3) * 2 + cc2];

    float c0 = g_c0;
    int chain = g_chain;
    float cf0 = 0, cf1 = 0, cf2 = 0, cf3 = 0, cf4 = 0;
    if (!chain) { cf0 = g_coef[0]; cf1 = g_coef[1]; cf2 = g_coef[2]; cf3 = g_coef[3]; cf4 = g_coef[4]; }

    float part = 0.f;
#pragma unroll
    for (int i = 0; i < 2; i++)
#pragma unroll
        for (int j = 0; j < 4; j++)
#pragma unroll
            for (int r = 0; r < 4; r++) {
                float l2 = fmaf(-2.0f, acc[i][j][r], sqa_r[i * 2 + (r >> 1)] + sqb_c[j * 2 + (r & 1)]);
                l2 = fmaxf(l2, 0.0f);
                float ks;
                if (chain) {
                    float x  = ex2f(-l2 * c0);
                    float x2 = x * x, x4 = x2 * x2, x8 = x4 * x4;
                    ks = x + x2 + x4 + x8 + x8 * x8;
                } else {
                    ks = ex2f(-l2 * cf0) + ex2f(-l2 * cf1) + ex2f(-l2 * cf2)
                       + ex2f(-l2 * cf3) + ex2f(-l2 * cf4);
                }
                part = fmaf(ks, wacc[i][j][r], part);
            }
    if (ti != tj) part *= 2.0f;

#pragma unroll
    for (int off = 16; off; off >>= 1) part += __shfl_xor_sync(0xffffffffu, part, off);
    if (lane == 0) sred[wid] = part;
    __syncthreads();
    if (tid == 0) {
        float s = 0.f;
#pragma unroll
        for (int w = 0; w < 16; w++) s += sred[w];
        atomicAdd(&g_loss, (double)s);
    }
}

__global__ void k_out(float* out) {
    out[0] = (float)(g_loss * (double)g_inv_nidx);
}

// ======================= launch =======================
extern "C" void kernel_launch(void* const* d_in, const int* in_sizes, int n_in,
                              void* d_out, int out_size) {
    const float* src = (const float*)d_in[0];
    const float* tgt = (const float*)d_in[1];
    const int*   sl  = (const int*)d_in[2];
    const float* tl  = (const float*)d_in[3];
    float* out = (float*)d_out;

    cudaFuncSetAttribute(k_main, cudaFuncAttributeMaxDynamicSharedMemorySize, SMEM_TOTAL);

    k_init<<<1, 64>>>();
    k_colsum<<<64, 256>>>(src, tgt);
    k_sq<<<1024, 256>>>(src, tgt);
    k_split<<<2048, 256>>>(src, tgt);
    k_label<<<16, 256>>>(sl, tl);
    k_finalize<<<1, 256>>>();
    k_buildV<<<32, 256>>>(sl, tl);
    k_main<<<NTILEPAIRS, 512, SMEM_TOTAL>>>();
    k_out<<<1, 1>>>(out);
}